// round 12
// baseline (speedup 1.0000x reference)
#include <cuda_runtime.h>
#include <cuda_bf16.h>

// TransferMatrixMethod: B=256, L=64 (62 interior), W=512.
// R11 structure (best: 8.86us) + MUFU HALVING:
//   All rounds R4-R11 are MUFU-pipe-bound (sincos = 2 MUFU/point-layer,
//   pipe at 75-77% = achievable max; elapsed ~= MUFU_cycles/0.76).
//   Fix: compute sincos once per layer (lane 0); lane 1 phase differs by
//   delta = nd*(k1-k0), |delta|<=0.024, so derive it by a 2nd-order
//   rotation on the FMA pipe:
//     cd = 1 - delta^2/2
//     s1 = s0*cd + c0*delta ;  c1 = c0*cd - s0*delta
//   (error delta^3/6 <= 2e-6/layer, ~6e-5 accumulated; tolerance 1e-3)
//
// Layer matrices [[a, ib],[ic, d]] closed under multiplication; track
// A,B,C,Dt(=-D), f32x2 lanes = 2 adjacent wavelengths. 2-way layer split,
// combine via shuffle xor 16 (verified R4/R11).

#define NLAYERS 62
#define HALF_L  31
#define LTOT    64
#define WDIM    512
#define TPB     128

typedef unsigned long long u64;

__device__ __forceinline__ u64 pack2(float lo, float hi) {
    u64 r;
    asm("mov.b64 %0, {%1, %2};" : "=l"(r) : "f"(lo), "f"(hi));
    return r;
}
__device__ __forceinline__ void unpack2(float& lo, float& hi, u64 v) {
    asm("mov.b64 {%0, %1}, %2;" : "=f"(lo), "=f"(hi) : "l"(v));
}
__device__ __forceinline__ u64 mul2(u64 a, u64 b) {
    u64 r;
    asm("mul.rn.f32x2 %0, %1, %2;" : "=l"(r) : "l"(a), "l"(b));
    return r;
}
__device__ __forceinline__ u64 fma2(u64 a, u64 b, u64 c) {
    u64 r;
    asm("fma.rn.f32x2 %0, %1, %2, %3;" : "=l"(r) : "l"(a), "l"(b), "l"(c));
    return r;
}
__device__ __forceinline__ u64 neg2(u64 a) {
    return a ^ 0x8000000080000000ULL;
}

__global__ __launch_bounds__(TPB, 7)
void tmm_kernel(const float* __restrict__ n_layers,
                const float* __restrict__ d_layers,
                const float* __restrict__ wavelengths,
                float* __restrict__ out)
{
    const int b   = blockIdx.x >> 2;            // 0..255
    const int q   = blockIdx.x & 3;             // quarter of wavelength axis
    const int t   = threadIdx.x;                // 0..127
    const int lid = t & 31;
    const int wrp = t >> 5;                     // warp in block, 0..3
    const int half  = lid >> 4;                 // 0: layers 0..30, 1: 31..61
    const int chain = wrp * 16 + (lid & 15);    // 0..63 within block
    const int w0    = (q * 64 + chain) * 2;     // even wavelength index

    __shared__ float s_nd[NLAYERS + 1];  // n*d; [62] = pad for prefetch
    __shared__ u64   s_n2[NLAYERS];      // {n, n}
    __shared__ u64   s_mr2[NLAYERS];     // {-1/(n+eps), -1/(n+eps)}
    __shared__ float s_nin, s_nsub;

    const float* nrow = n_layers + b * LTOT;
    const float* drow = d_layers + b * LTOT;

    if (t < NLAYERS) {
        float nv = nrow[t + 1];
        float dv = drow[t + 1];
        s_nd[t]  = nv * dv;
        s_n2[t]  = pack2(nv, nv);
        float mr = -1.0f / (nv + 1e-8f);
        s_mr2[t] = pack2(mr, mr);
    }
    if (t == NLAYERS)     s_nin  = nrow[0];
    if (t == NLAYERS + 1) s_nsub = nrow[LTOT - 1];
    if (t == NLAYERS + 2) s_nd[NLAYERS] = 0.0f;   // prefetch overread pad
    __syncthreads();

    const float TWO_PI = 6.28318530717958647692f;
    const float2 lam = *reinterpret_cast<const float2*>(wavelengths + w0);
    const float k0 = __fdividef(TWO_PI, lam.x);
    const float k1 = __fdividef(TWO_PI, lam.y);
    const float dk = k1 - k0;                    // |nd*dk| <= ~0.024

    const int base = half * HALF_L;

    u64 A  = pack2(1.0f, 1.0f);
    u64 Bv = pack2(0.0f, 0.0f);
    u64 C  = pack2(0.0f, 0.0f);
    u64 Dt = pack2(-1.0f, -1.0f);   // -D

    // prologue: trig + rotation constants for l = 0
    // (|phi| <= ~12: inside MUFU accurate range, verified R2-R11)
    float s0p, c0p, dlp, cdp;
    {
        const float nd = s_nd[base];
        __sincosf(nd * k0, &s0p, &c0p);
        dlp = nd * dk;
        cdp = fmaf(dlp * dlp, -0.5f, 1.0f);
    }

    #pragma unroll
    for (int l = 0; l < HALF_L; ++l) {
        // ---- consume: derive lane 1 trig by small rotation (FMA pipe) ----
        const float s0 = s0p, c0 = c0p, dl = dlp, cd = cdp;
        const float s1 = fmaf(c0, dl,  s0 * cd);
        const float c1 = fmaf(s0, -dl, c0 * cd);
        const u64 sp2 = pack2(s0, s1);
        const u64 cp2 = pack2(c0, c1);

        // ---- prefetch trig for layer l+1 (unconditional; padded table) ----
        {
            const float nd = s_nd[base + l + 1];
            __sincosf(nd * k0, &s0p, &c0p);
            dlp = nd * dk;
            cdp = fmaf(dlp * dlp, -0.5f, 1.0f);
        }

        // ---- matrix update for layer l (R4/R11 verbatim) ----
        const u64 ns2  = mul2(sp2, s_n2[base + l]);    // { n*sin }
        const u64 msr2 = mul2(sp2, s_mr2[base + l]);   // { -sin/(n+eps) }

        u64 nA = fma2(ns2,  Bv, mul2(cp2, A));
        u64 nB = fma2(msr2, A,  mul2(cp2, Bv));
        u64 nC = fma2(ns2,  Dt, mul2(cp2, C));
        u64 nD = fma2(msr2, C,  mul2(cp2, Dt));
        A = nA; Bv = nB; C = nC; Dt = nD;
    }

    // exchange halves: lane i <-> lane i^16 (verified R4/R11)
    const unsigned FULL = 0xffffffffu;
    u64 Ay  = __shfl_xor_sync(FULL, A,  16);
    u64 By  = __shfl_xor_sync(FULL, Bv, 16);
    u64 Cy  = __shfl_xor_sync(FULL, C,  16);
    u64 Dty = __shfl_xor_sync(FULL, Dt, 16);

    if (half == 0) {
        // combine: M = X * Y   (X = own = layers 1..31, Y = partner)
        u64 Dy = neg2(Dty);
        u64 fA = fma2(neg2(Bv), Cy, mul2(A, Ay));        // Ax*Ay - Bx*Cy
        u64 fB = fma2(Bv, Dy,       mul2(A, By));        // Ax*By + Bx*Dy
        u64 fC = fma2(neg2(Dt), Cy, mul2(C, Ay));        // Cx*Ay + Dx*Cy
        u64 fD = fma2(neg2(C),  By, mul2(neg2(Dt), Dy)); // Dx*Dy - Cx*By

        float A0, A1, B0, B1, C0, C1, D0, D1;
        unpack2(A0, A1, fA);
        unpack2(B0, B1, fB);
        unpack2(C0, C1, fC);
        unpack2(D0, D1, fD);

        const float nin  = s_nin;
        const float nsub = s_nsub;

        float R[2];
        #pragma unroll
        for (int i = 0; i < 2; ++i) {
            const float a  = i ? A1 : A0;
            const float bb = i ? B1 : B0;
            const float c  = i ? C1 : C0;
            const float d  = i ? D1 : D0;

            const float Er = a + 1e-9f;
            const float Ei = bb * nsub;
            const float Hr = d * nsub;
            const float Hi = c;

            const float numr = fmaf(nin, Er, -Hr);
            const float numi = fmaf(nin, Ei, -Hi);
            const float denr = fmaf(nin, Er,  Hr);
            const float deni = fmaf(nin, Ei,  Hi);

            const float num2 = fmaf(numr, numr, numi * numi);
            const float den2 = fmaf(denr, denr, deni * deni);
            R[i] = num2 / den2;
        }

        *reinterpret_cast<float2*>(out + b * WDIM + w0) = make_float2(R[0], R[1]);
    }
}

extern "C" void kernel_launch(void* const* d_in, const int* in_sizes, int n_in,
                              void* d_out, int out_size)
{
    const float* n_layers    = (const float*)d_in[0];  // (256, 64)
    const float* d_layers    = (const float*)d_in[1];  // (256, 64)
    const float* wavelengths = (const float*)d_in[2];  // (512,)
    float* out = (float*)d_out;                        // (256, 512)

    tmm_kernel<<<1024, TPB>>>(n_layers, d_layers, wavelengths, out);
}

// round 13
// speedup vs baseline: 1.0239x; 1.0239x over previous
#include <cuda_runtime.h>
#include <cuda_bf16.h>

// TransferMatrixMethod: B=256, L=64 (62 interior), W=512.
// R11 structure (best: 8.86us kernel) + PIPE BALANCING:
//   R11 was double-pipe-bound: MUFU ~6.9K cyc AND FMA ~6.1K cyc per SMSP.
//   R12 (rotation on ALL layers) pushed FMA to 7.3K -> slower.
//   Fix: rotation trick on only f=11/31 of layers (j%3==1):
//     MUFU -> ~4.6K, FMA -> ~5.6K, pipes balanced.
//   Rotation (layers j%3==1): sincos once (lane 0), lane 1 via 2nd-order
//   small-angle rotation, delta = nd*(k1-k0), |delta|<=0.024:
//     cd = 1 - d^2/2; s1 = s0*cd + c0*d; c1 = c0*cd - s0*d
//   error ~2e-6/layer * 11 layers ~ 2.3e-5 << 1e-3 tolerance.
//
// Layer matrices [[a, ib],[ic, d]] closed under multiplication; track
// A,B,C,Dt(=-D), f32x2 lanes = 2 adjacent wavelengths. 2-way layer split,
// combine via shuffle xor 16 (verified R4/R11). Depth-1 trig prefetch,
// launch_bounds(128,7) for the 70-reg budget (verified R11).

#define NLAYERS 62
#define HALF_L  31
#define LTOT    64
#define WDIM    512
#define TPB     128

typedef unsigned long long u64;

__device__ __forceinline__ u64 pack2(float lo, float hi) {
    u64 r;
    asm("mov.b64 %0, {%1, %2};" : "=l"(r) : "f"(lo), "f"(hi));
    return r;
}
__device__ __forceinline__ void unpack2(float& lo, float& hi, u64 v) {
    asm("mov.b64 {%0, %1}, %2;" : "=f"(lo), "=f"(hi) : "l"(v));
}
__device__ __forceinline__ u64 mul2(u64 a, u64 b) {
    u64 r;
    asm("mul.rn.f32x2 %0, %1, %2;" : "=l"(r) : "l"(a), "l"(b));
    return r;
}
__device__ __forceinline__ u64 fma2(u64 a, u64 b, u64 c) {
    u64 r;
    asm("fma.rn.f32x2 %0, %1, %2, %3;" : "=l"(r) : "l"(a), "l"(b), "l"(c));
    return r;
}
__device__ __forceinline__ u64 neg2(u64 a) {
    return a ^ 0x8000000080000000ULL;
}

__global__ __launch_bounds__(TPB, 7)
void tmm_kernel(const float* __restrict__ n_layers,
                const float* __restrict__ d_layers,
                const float* __restrict__ wavelengths,
                float* __restrict__ out)
{
    const int b   = blockIdx.x >> 2;            // 0..255
    const int q   = blockIdx.x & 3;             // quarter of wavelength axis
    const int t   = threadIdx.x;                // 0..127
    const int lid = t & 31;
    const int wrp = t >> 5;                     // warp in block, 0..3
    const int half  = lid >> 4;                 // 0: layers 0..30, 1: 31..61
    const int chain = wrp * 16 + (lid & 15);    // 0..63 within block
    const int w0    = (q * 64 + chain) * 2;     // even wavelength index

    __shared__ float s_nd[NLAYERS + 1];  // n*d; [62] = pad for prefetch
    __shared__ u64   s_n2[NLAYERS];      // {n, n}
    __shared__ u64   s_mr2[NLAYERS];     // {-1/(n+eps), -1/(n+eps)}
    __shared__ float s_nin, s_nsub;

    const float* nrow = n_layers + b * LTOT;
    const float* drow = d_layers + b * LTOT;

    if (t < NLAYERS) {
        float nv = nrow[t + 1];
        float dv = drow[t + 1];
        s_nd[t]  = nv * dv;
        s_n2[t]  = pack2(nv, nv);
        float mr = -1.0f / (nv + 1e-8f);
        s_mr2[t] = pack2(mr, mr);
    }
    if (t == NLAYERS)     s_nin  = nrow[0];
    if (t == NLAYERS + 1) s_nsub = nrow[LTOT - 1];
    if (t == NLAYERS + 2) s_nd[NLAYERS] = 0.0f;   // prefetch overread pad
    __syncthreads();

    const float TWO_PI = 6.28318530717958647692f;
    const float2 lam = *reinterpret_cast<const float2*>(wavelengths + w0);
    const float k0 = __fdividef(TWO_PI, lam.x);
    const float k1 = __fdividef(TWO_PI, lam.y);
    const float dk = k1 - k0;                    // |nd*dk| <= ~0.024

    const int base = half * HALF_L;

    u64 A  = pack2(1.0f, 1.0f);
    u64 Bv = pack2(0.0f, 0.0f);
    u64 C  = pack2(0.0f, 0.0f);
    u64 Dt = pack2(-1.0f, -1.0f);   // -D

    // prologue: trig for j = 0 (direct dual sincos)
    // (|phi| <= ~12: inside MUFU accurate range, verified R2-R12)
    float s0, c0, s1, c1;
    {
        const float nd = s_nd[base];
        __sincosf(nd * k0, &s0, &c0);
        __sincosf(nd * k1, &s1, &c1);
    }

    #pragma unroll
    for (int l = 0; l < HALF_L; ++l) {
        const u64 sp2 = pack2(s0, s1);
        const u64 cp2 = pack2(c0, c1);

        // ---- prefetch trig for layer l+1 (unconditional; padded table) ----
        // Pipe balance: layers with (l+1)%3==1 use one sincos + FMA-pipe
        // rotation for lane 1; others use direct dual sincos.
        {
            const float nd = s_nd[base + l + 1];
            if (((l + 1) % 3) == 1) {
                __sincosf(nd * k0, &s0, &c0);
                const float dl = nd * dk;
                const float cd = fmaf(dl * dl, -0.5f, 1.0f);
                s1 = fmaf(c0, dl,  s0 * 0.0f + s0 * cd);  // s0*cd + c0*dl
                s1 = fmaf(c0, dl,  s0 * cd);
                c1 = fmaf(s0, -dl, c0 * cd);
            } else {
                __sincosf(nd * k0, &s0, &c0);
                __sincosf(nd * k1, &s1, &c1);
            }
        }

        // ---- matrix update for layer l (R4/R11 verbatim) ----
        const u64 ns2  = mul2(sp2, s_n2[base + l]);    // { n*sin }
        const u64 msr2 = mul2(sp2, s_mr2[base + l]);   // { -sin/(n+eps) }

        u64 nA = fma2(ns2,  Bv, mul2(cp2, A));
        u64 nB = fma2(msr2, A,  mul2(cp2, Bv));
        u64 nC = fma2(ns2,  Dt, mul2(cp2, C));
        u64 nD = fma2(msr2, C,  mul2(cp2, Dt));
        A = nA; Bv = nB; C = nC; Dt = nD;
    }

    // exchange halves: lane i <-> lane i^16 (verified R4/R11)
    const unsigned FULL = 0xffffffffu;
    u64 Ay  = __shfl_xor_sync(FULL, A,  16);
    u64 By  = __shfl_xor_sync(FULL, Bv, 16);
    u64 Cy  = __shfl_xor_sync(FULL, C,  16);
    u64 Dty = __shfl_xor_sync(FULL, Dt, 16);

    if (half == 0) {
        // combine: M = X * Y   (X = own = layers 1..31, Y = partner)
        u64 Dy = neg2(Dty);
        u64 fA = fma2(neg2(Bv), Cy, mul2(A, Ay));        // Ax*Ay - Bx*Cy
        u64 fB = fma2(Bv, Dy,       mul2(A, By));        // Ax*By + Bx*Dy
        u64 fC = fma2(neg2(Dt), Cy, mul2(C, Ay));        // Cx*Ay + Dx*Cy
        u64 fD = fma2(neg2(C),  By, mul2(neg2(Dt), Dy)); // Dx*Dy - Cx*By

        float A0, A1, B0, B1, C0, C1, D0, D1;
        unpack2(A0, A1, fA);
        unpack2(B0, B1, fB);
        unpack2(C0, C1, fC);
        unpack2(D0, D1, fD);

        const float nin  = s_nin;
        const float nsub = s_nsub;

        float R[2];
        #pragma unroll
        for (int i = 0; i < 2; ++i) {
            const float a  = i ? A1 : A0;
            const float bb = i ? B1 : B0;
            const float c  = i ? C1 : C0;
            const float d  = i ? D1 : D0;

            const float Er = a + 1e-9f;
            const float Ei = bb * nsub;
            const float Hr = d * nsub;
            const float Hi = c;

            const float numr = fmaf(nin, Er, -Hr);
            const float numi = fmaf(nin, Ei, -Hi);
            const float denr = fmaf(nin, Er,  Hr);
            const float deni = fmaf(nin, Ei,  Hi);

            const float num2 = fmaf(numr, numr, numi * numi);
            const float den2 = fmaf(denr, denr, deni * deni);
            R[i] = num2 / den2;
        }

        *reinterpret_cast<float2*>(out + b * WDIM + w0) = make_float2(R[0], R[1]);
    }
}

extern "C" void kernel_launch(void* const* d_in, const int* in_sizes, int n_in,
                              void* d_out, int out_size)
{
    const float* n_layers    = (const float*)d_in[0];  // (256, 64)
    const float* d_layers    = (const float*)d_in[1];  // (256, 64)
    const float* wavelengths = (const float*)d_in[2];  // (512,)
    float* out = (float*)d_out;                        // (256, 512)

    tmm_kernel<<<1024, TPB>>>(n_layers, d_layers, wavelengths, out);
}